// round 13
// baseline (speedup 1.0000x reference)
#include <cuda_runtime.h>
#include <cstdint>

// Problem constants
#define B_    32
#define C_    2
#define H_    512
#define W_    512
#define HP    (H_ * W_)          // 262144 elements per heatmap
#define NMAPS (B_ * C_)          // 64 heatmaps
#define SPLIT 16                 // chunks per heatmap
#define CHUNK (HP / SPLIT)       // 16384 elements per block
#define NBLK  (NMAPS * SPLIT)    // 1024 blocks in kernel 1
#define NTHR  256
#define UBAT  4                  // float4-pairs front-batched per phase

// Deterministic partial scratch (no allocations allowed)
__device__ float              g_s [NBLK];
__device__ float              g_sx[NBLK];
__device__ float              g_sy[NBLK];
__device__ unsigned long long g_t [NBLK];

// Monotone float -> uint key (total order matching float compare)
__device__ __forceinline__ unsigned int fkey(float v) {
    unsigned int u = __float_as_uint(v);
    return (u & 0x80000000u) ? ~u : (u | 0x80000000u);
}

__global__ __launch_bounds__(NTHR)
void dsnt_pass_kernel(const float* __restrict__ inp,
                      const float* __restrict__ tgt) {
    const int blk = blockIdx.x;        // 0..NBLK-1
    const int h   = blk >> 4;          // heatmap index
    const int j   = blk & (SPLIT - 1); // chunk within heatmap

    const size_t base = (size_t)h * HP + (size_t)j * CHUNK;
    const float4* __restrict__ ip = (const float4*)(inp + base);
    const float4* __restrict__ tp = (const float4*)(tgt + base);

    const int t      = threadIdx.x;
    const int ebase0 = j * CHUNK;

    // Loop-invariant coordinates: per-thread stride = 256 float4 = 1024 elems
    // = exactly 2 rows. cx0 constant; cy advances by +2.0 per iteration.
    const int   te    = t * 4;                               // 0..1020
    const float cx0   = (float)((te & 511) + 1);             // col+1 (invariant)
    const float cyb   = (float)((ebase0 >> 9) + (te >> 9) + 1); // row+1 at iter 0

    float s = 0.f, sx = 0.f, sy = 0.f;
    float tv = -3.0e38f;
    int   ti = 0;

    const int ITERS = CHUNK / 4 / NTHR;   // 16 float4s per thread
    #pragma unroll
    for (int o = 0; o < ITERS; o += UBAT) {
        float4 vv[UBAT], gg[UBAT];
        // Phase 1: issue all 8 independent streaming LDG.128s (high MLP)
        #pragma unroll
        for (int u = 0; u < UBAT; u++) {
            const int f = t + (o + u) * NTHR;
            vv[u] = __ldcs(&ip[f]);
            gg[u] = __ldcs(&tp[f]);
        }
        // Phase 2: compute (no int coordinate math in steady state)
        #pragma unroll
        for (int u = 0; u < UBAT; u++) {
            const int   q  = o + u;
            const float cy = cyb + 2.0f * (float)q;   // folds to immediate add

            const float w0 = __expf(vv[u].x);
            const float w1 = __expf(vv[u].y);
            const float w2 = __expf(vv[u].z);
            const float w3 = __expf(vv[u].w);
            const float ws = (w0 + w1) + (w2 + w3);

            s += ws;
            sy = fmaf(ws, cy, sy);
            // sum_k w_k*(cx0+k) = ws*cx0 + (w1 + 2*w2 + 3*w3)
            sx = fmaf(ws, cx0, sx) + fmaf(2.f, w2, fmaf(3.f, w3, w1));

            // cheap steady-state argmax: max tree, index resolved only on change
            const float m4 = fmaxf(fmaxf(gg[u].x, gg[u].y), fmaxf(gg[u].z, gg[u].w));
            if (m4 > tv) {
                tv = m4;
                const int e0 = ebase0 + (t + q * NTHR) * 4;  // rare path only
                ti = (gg[u].x == m4) ? e0
                   : (gg[u].y == m4) ? e0 + 1
                   : (gg[u].z == m4) ? e0 + 2
                   :                   e0 + 3;
            }
        }
    }

    // pack argmax: higher value wins; on equal value, smaller index wins
    unsigned long long key =
        ((unsigned long long)fkey(tv) << 32) | (unsigned int)(HP - 1 - ti);

    // warp reduce
    #pragma unroll
    for (int o = 16; o > 0; o >>= 1) {
        s  += __shfl_down_sync(0xFFFFFFFFu, s,  o);
        sx += __shfl_down_sync(0xFFFFFFFFu, sx, o);
        sy += __shfl_down_sync(0xFFFFFFFFu, sy, o);
        unsigned long long ok = __shfl_down_sync(0xFFFFFFFFu, key, o);
        if (ok > key) key = ok;
    }

    __shared__ float              rs[NTHR / 32], rx[NTHR / 32], ry[NTHR / 32];
    __shared__ unsigned long long rt[NTHR / 32];
    const int lane = t & 31, wid = t >> 5;
    if (lane == 0) { rs[wid] = s; rx[wid] = sx; ry[wid] = sy; rt[wid] = key; }
    __syncthreads();

    if (wid == 0) {
        s   = (lane < NTHR / 32) ? rs[lane] : 0.f;
        sx  = (lane < NTHR / 32) ? rx[lane] : 0.f;
        sy  = (lane < NTHR / 32) ? ry[lane] : 0.f;
        key = (lane < NTHR / 32) ? rt[lane] : 0ull;
        #pragma unroll
        for (int o = 4; o > 0; o >>= 1) {
            s  += __shfl_down_sync(0xFFFFFFFFu, s,  o);
            sx += __shfl_down_sync(0xFFFFFFFFu, sx, o);
            sy += __shfl_down_sync(0xFFFFFFFFu, sy, o);
            unsigned long long ok = __shfl_down_sync(0xFFFFFFFFu, key, o);
            if (ok > key) key = ok;
        }
        if (lane == 0) {
            g_s [blk] = s;
            g_sx[blk] = sx;
            g_sy[blk] = sy;
            g_t [blk] = key;
        }
    }
}

// 1024 threads: one partial per thread, segmented (width-16) shuffle reduce.
__global__ __launch_bounds__(NBLK)
void dsnt_final_kernel(float* __restrict__ out) {
    const int t = threadIdx.x;            // 0..1023 = partial index
    const int h = t >> 4;                 // heatmap 0..63
    const int sl = t & 15;                // slot within heatmap

    float s  = g_s [t];
    float sx = g_sx[t];
    float sy = g_sy[t];
    unsigned long long key = g_t[t];

    // reduce across the 16 slots of each heatmap (segments aligned in warps)
    #pragma unroll
    for (int o = 8; o > 0; o >>= 1) {
        s  += __shfl_down_sync(0xFFFFFFFFu, s,  o, 16);
        sx += __shfl_down_sync(0xFFFFFFFFu, sx, o, 16);
        sy += __shfl_down_sync(0xFFFFFFFFu, sy, o, 16);
        unsigned long long ok = __shfl_down_sync(0xFFFFFFFFu, key, o, 16);
        if (ok > key) key = ok;
    }

    __shared__ float spx[NMAPS], spy[NMAPS], stx[NMAPS], sty[NMAPS];
    __shared__ float ed[NMAPS], dd[B_];

    if (sl == 0) {
        const float px = sx / s;          // pixel coordinate (1-based)
        const float py = sy / s;
        const int idx = HP - 1 - (int)(key & 0xFFFFFFFFu);
        const float tx = (float)((idx & (W_ - 1)) + 1);
        const float ty = (float)((idx >> 9) + 1);

        // pred_coords [64,2] then true_coords [64,2], each (coord - 1)
        out[4 + 2 * h]           = px - 1.f;
        out[4 + 2 * h + 1]       = py - 1.f;
        out[4 + 128 + 2 * h]     = tx - 1.f;
        out[4 + 128 + 2 * h + 1] = ty - 1.f;

        spx[h] = px; spy[h] = py; stx[h] = tx; sty[h] = ty;
        const float dx = tx - px, dy = ty - py;
        ed[h] = sqrtf(dx * dx + dy * dy);
    }
    __syncthreads();

    if (t < B_) {
        const int b = t;
        const int e = 2 * b;
        const float vpx = spx[e] - spx[e + 1];
        const float vpy = spy[e] - spy[e + 1];
        const float vtx = stx[e] - stx[e + 1];
        const float vty = sty[e] - sty[e + 1];
        const float pd = sqrtf(vpx * vpx + vpy * vpy);
        const float td = sqrtf(vtx * vtx + vty * vty);
        dd[b] = fabsf(pd - td);
    }
    __syncthreads();

    if (t == 0) {
        float si = 0.f, ss = 0.f, sd = 0.f;
        #pragma unroll
        for (int b = 0; b < B_; b++) {
            si += ed[2 * b];
            ss += ed[2 * b + 1];
            sd += dd[b];
        }
        const float bn = (float)B_;
        out[0] = si / bn;
        out[1] = ss / bn;
        out[2] = (si + ss) / bn;
        out[3] = sd / bn;
    }
}

extern "C" void kernel_launch(void* const* d_in, const int* in_sizes, int n_in,
                              void* d_out, int out_size) {
    const float* inp = (const float*)d_in[0];
    const float* tgt = (const float*)d_in[1];
    float* out = (float*)d_out;

    dsnt_pass_kernel<<<NBLK, NTHR>>>(inp, tgt);
    dsnt_final_kernel<<<1, NBLK>>>(out);
}